// round 1
// baseline (speedup 1.0000x reference)
#include <cuda_runtime.h>
#include <cuda_bf16.h>

// Problem constants
#define BB  4
#define CX  16
#define CA  8
#define C1  16
#define NN  1024
#define DD  64
#define BETA 0.02f
#define RSQRT10 0.3162277660168379f

// smem row stride (floats) for 1024-wide panels: 1028 -> 16B aligned, rotates banks
#define LSTR 1028

// Scratch (static __device__ arrays; no dynamic allocation)
__device__ __align__(16) float g_S[BB * NN * NN];         // 16.8 MB
__device__ __align__(16) float g_Amean[BB * NN * NN];     // 16.8 MB
__device__ __align__(16) __nv_bfloat16 g_xbf[BB * CX * NN * DD];  // 8.4 MB
__device__ __align__(16) __nv_bfloat16 g_mbf[BB * C1 * NN * DD];  // 8.4 MB

// ---------------------------------------------------------------------------
// PTX helpers
// ---------------------------------------------------------------------------
__device__ __forceinline__ unsigned sptr(const void* p) {
    return (unsigned)__cvta_generic_to_shared(p);
}

__device__ __forceinline__ void ldsm4(unsigned a[4], unsigned addr) {
    asm volatile("ldmatrix.sync.aligned.m8n8.x4.shared.b16 {%0,%1,%2,%3}, [%4];"
                 : "=r"(a[0]), "=r"(a[1]), "=r"(a[2]), "=r"(a[3]) : "r"(addr));
}

__device__ __forceinline__ void mma16816(float c[4], const unsigned a[4],
                                         unsigned b0, unsigned b1) {
    asm volatile(
        "mma.sync.aligned.m16n8k16.row.col.f32.bf16.bf16.f32 "
        "{%0,%1,%2,%3}, {%4,%5,%6,%7}, {%8,%9}, {%0,%1,%2,%3};"
        : "+f"(c[0]), "+f"(c[1]), "+f"(c[2]), "+f"(c[3])
        : "r"(a[0]), "r"(a[1]), "r"(a[2]), "r"(a[3]), "r"(b0), "r"(b1));
}

__device__ __forceinline__ void cpasync16(unsigned dst, const void* src) {
    asm volatile("cp.async.cg.shared.global [%0], [%1], 16;" :: "r"(dst), "l"(src));
}
#define CP_COMMIT() asm volatile("cp.async.commit_group;")
#define CP_WAIT1()  asm volatile("cp.async.wait_group 1;")
#define CP_WAIT0()  asm volatile("cp.async.wait_group 0;")

// ---------------------------------------------------------------------------
// Swizzled bf16 tile helpers. Tiles are [rows][64] bf16, 128B/row; 16B chunks
// are XOR-swizzled: chunk' = chunk ^ (row & 7)  -> conflict-free ldmatrix.
// ---------------------------------------------------------------------------
__device__ __forceinline__ void prefetch_chunk128(const __nv_bfloat16* src,
                                                  __nv_bfloat16* dst, int tid) {
    // 128 rows x 64 bf16 = 1024 x 16B ops, 256 threads x 4
#pragma unroll
    for (int q = 0; q < 4; q++) {
        int id = tid + q * 256;
        int r = id >> 3, cc = id & 7;
        cpasync16(sptr(dst + r * 64 + (((cc) ^ (r & 7)) << 3)),
                  src + r * 64 + cc * 8);
    }
}

__device__ __forceinline__ void load_tile16(const __nv_bfloat16* src,
                                            __nv_bfloat16* dst, int tid) {
    if (tid < 128) {
        int r = tid >> 3, cc = tid & 7;
        *(uint4*)(dst + r * 64 + ((cc ^ (r & 7)) << 3)) =
            *(const uint4*)(src + r * 64 + cc * 8);
    }
}

// Warp computes C[16 x 16] = Xi[16 x 64] * Xj[n0:n0+16, 0:64]^T  (bf16, f32 acc)
__device__ __forceinline__ void warp_gemm16x16(const __nv_bfloat16* xi_s,
                                               const __nv_bfloat16* xj_s,
                                               int n0, int lane, float acc[8]) {
    const int ar  = (lane & 7) + (((lane >> 3) & 1) << 3); // A row 0..15
    const int ak8 = (lane >> 4);                           // +8 k for lanes 16-31
    const int m   = lane >> 3;
    const int br  = n0 + (lane & 7) + ((m >> 1) << 3);     // B row
    const int bk8 = (m & 1);
#pragma unroll
    for (int ks = 0; ks < 4; ks++) {
        const int kc = ks * 2; // base 16B-chunk index of this k-step
        unsigned a[4], b[4];
        unsigned aaddr = sptr(xi_s + ar * 64 + (((kc + ak8) ^ (ar & 7)) << 3));
        unsigned baddr = sptr(xj_s + br * 64 + (((kc + bk8) ^ (br & 7)) << 3));
        ldsm4(a, aaddr);
        ldsm4(b, baddr);
        mma16816(acc,     a, b[0], b[1]);
        mma16816(acc + 4, a, b[2], b[3]);
    }
}

// ---------------------------------------------------------------------------
// Prep kernels
// ---------------------------------------------------------------------------
__global__ void k_amean(const float* __restrict__ A) {
    int idx = blockIdx.x * blockDim.x + threadIdx.x; // over BB*NN*NN/4 float4
    const int per_b = NN * NN / 4;
    if (idx >= BB * per_b) return;
    int b = idx / per_b;
    int r = idx - b * per_b;
    const float4* base = (const float4*)A + (size_t)b * CA * per_b + r;
    float4 s = make_float4(0.f, 0.f, 0.f, 0.f);
#pragma unroll
    for (int ca = 0; ca < CA; ca++) {
        float4 v = base[(size_t)ca * per_b];
        s.x += v.x; s.y += v.y; s.z += v.z; s.w += v.w;
    }
    s.x *= 0.125f; s.y *= 0.125f; s.z *= 0.125f; s.w *= 0.125f;
    ((float4*)g_Amean)[idx] = s;
}

__global__ void k_convx(const float* __restrict__ src) {
    int idx = blockIdx.x * blockDim.x + threadIdx.x; // over 4M/4 float4
    if (idx >= BB * CX * NN * DD / 4) return;
    float4 v = ((const float4*)src)[idx];
    __nv_bfloat162 p0 = __floats2bfloat162_rn(v.x, v.y);
    __nv_bfloat162 p1 = __floats2bfloat162_rn(v.z, v.w);
    uint2 u;
    u.x = *reinterpret_cast<unsigned*>(&p0);
    u.y = *reinterpret_cast<unsigned*>(&p1);
    ((uint2*)g_xbf)[idx] = u;
}

__global__ void k_convm(const float* __restrict__ src) {
    int idx = blockIdx.x * blockDim.x + threadIdx.x;
    if (idx >= BB * C1 * NN * DD / 4) return;
    float4 v = ((const float4*)src)[idx];
    __nv_bfloat162 p0 = __floats2bfloat162_rn(v.x, v.y);
    __nv_bfloat162 p1 = __floats2bfloat162_rn(v.z, v.w);
    uint2 u;
    u.x = *reinterpret_cast<unsigned*>(&p0);
    u.y = *reinterpret_cast<unsigned*>(&p1);
    ((uint2*)g_mbf)[idx] = u;
}

// ---------------------------------------------------------------------------
// K_S: S[b,i,j] = (1/16) sum_c softmax_row(x_c @ x_c^T)[i,j]
// Block = (itile of 16 rows, b), 256 threads (8 warps).
// smem: S_acc[16][1028] + L[16][1028] + xi[16*64]bf16 + xj[2][128*64]bf16
// ---------------------------------------------------------------------------
#define SMEM_S (2 * 16 * LSTR * 4 + 16 * 64 * 2 + 2 * 128 * 64 * 2)

__global__ void __launch_bounds__(256, 1) k_S() {
    extern __shared__ char smraw[];
    float* S_acc = (float*)smraw;
    float* L     = S_acc + 16 * LSTR;
    __nv_bfloat16* xi = (__nv_bfloat16*)(L + 16 * LSTR);
    __nv_bfloat16* xj = xi + 16 * 64;

    const int tid = threadIdx.x, lane = tid & 31, w = tid >> 5;
    const int itile = blockIdx.x, b = blockIdx.y;
    const int i0 = itile * 16;

    for (int i = tid; i < 16 * LSTR; i += 256) S_acc[i] = 0.f;

    const __nv_bfloat16* xb = g_xbf + (size_t)b * CX * NN * DD;

    for (int c = 0; c < CX; c++) {
        const __nv_bfloat16* xc = xb + (size_t)c * NN * DD;
        __syncthreads();
        load_tile16(xc + i0 * 64, xi, tid);
        prefetch_chunk128(xc, xj, tid);
        CP_COMMIT();

        for (int jt = 0; jt < 8; jt++) {
            if (jt < 7) {
                prefetch_chunk128(xc + (jt + 1) * 128 * 64,
                                  xj + ((jt + 1) & 1) * (128 * 64), tid);
                CP_COMMIT();
                CP_WAIT1();
            } else {
                CP_WAIT0();
            }
            __syncthreads();
            float acc[8] = {0.f, 0.f, 0.f, 0.f, 0.f, 0.f, 0.f, 0.f};
            warp_gemm16x16(xi, xj + (jt & 1) * (128 * 64), w * 16, lane, acc);
            const int r0 = lane >> 2;
            const int gc = jt * 128 + w * 16 + (lane & 3) * 2;
            L[r0 * LSTR + gc]           = acc[0];
            L[r0 * LSTR + gc + 1]       = acc[1];
            L[(r0 + 8) * LSTR + gc]     = acc[2];
            L[(r0 + 8) * LSTR + gc + 1] = acc[3];
            L[r0 * LSTR + gc + 8]       = acc[4];
            L[r0 * LSTR + gc + 9]       = acc[5];
            L[(r0 + 8) * LSTR + gc + 8] = acc[6];
            L[(r0 + 8) * LSTR + gc + 9] = acc[7];
            __syncthreads();
        }

        // softmax: warp w owns rows 2w, 2w+1
#pragma unroll
        for (int rr = 0; rr < 2; rr++) {
            const int r = 2 * w + rr;
            float* Lr = L + r * LSTR;
            float m = -1e30f;
            for (int i = lane; i < 1024; i += 32) m = fmaxf(m, Lr[i]);
#pragma unroll
            for (int off = 16; off; off >>= 1)
                m = fmaxf(m, __shfl_xor_sync(0xffffffffu, m, off));
            float s = 0.f;
            for (int i = lane; i < 1024; i += 32) {
                float v = __expf(Lr[i] - m);
                Lr[i] = v;
                s += v;
            }
#pragma unroll
            for (int off = 16; off; off >>= 1)
                s += __shfl_xor_sync(0xffffffffu, s, off);
            const float inv = 0.0625f / s;  // includes 1/16 channel mean
            float* Sr = S_acc + r * LSTR;
            for (int i = lane; i < 1024; i += 32) Sr[i] += Lr[i] * inv;
        }
    }
    __syncthreads();
    float* out = g_S + ((size_t)b * NN + i0) * NN;
    for (int idx4 = tid; idx4 < 16 * 256; idx4 += 256) {
        int r = idx4 >> 8, c4 = idx4 & 255;
        ((float4*)(out + r * NN))[c4] = *(float4*)(S_acc + r * LSTR + c4 * 4);
    }
}

// ---------------------------------------------------------------------------
// K_main: per (c, itile, b): mm = mask_c mask_c^T tile;
//   A_out = A_mean + 0.02*sigmoid(S*mm/sqrt(10)); top-5 + gather + max.
// ---------------------------------------------------------------------------
#define SMEM_M (16 * LSTR * 4 + 16 * 64 * 2 + 2 * 128 * 64 * 2)

__global__ void __launch_bounds__(256, 2) k_main(const float* __restrict__ mask,
                                                 float* __restrict__ outA,
                                                 float* __restrict__ outM) {
    extern __shared__ char smraw[];
    float* Arow = (float*)smraw;                     // 16 x 1028
    __nv_bfloat16* mi = (__nv_bfloat16*)(Arow + 16 * LSTR);
    __nv_bfloat16* mj = mi + 16 * 64;

    const int tid = threadIdx.x, lane = tid & 31, w = tid >> 5;
    const int c = blockIdx.x, itile = blockIdx.y, b = blockIdx.z;
    const int i0 = itile * 16;

    const __nv_bfloat16* mc = g_mbf + (size_t)(b * C1 + c) * NN * DD;
    load_tile16(mc + i0 * 64, mi, tid);
    prefetch_chunk128(mc, mj, tid);
    CP_COMMIT();

    for (int jt = 0; jt < 8; jt++) {
        if (jt < 7) {
            prefetch_chunk128(mc + (jt + 1) * 128 * 64,
                              mj + ((jt + 1) & 1) * (128 * 64), tid);
            CP_COMMIT();
            CP_WAIT1();
        } else {
            CP_WAIT0();
        }
        __syncthreads();
        float acc[8] = {0.f, 0.f, 0.f, 0.f, 0.f, 0.f, 0.f, 0.f};
        warp_gemm16x16(mi, mj + (jt & 1) * (128 * 64), w * 16, lane, acc);
        const int r0 = lane >> 2;
        const int gc = jt * 128 + w * 16 + (lane & 3) * 2;
        Arow[r0 * LSTR + gc]           = acc[0];
        Arow[r0 * LSTR + gc + 1]       = acc[1];
        Arow[(r0 + 8) * LSTR + gc]     = acc[2];
        Arow[(r0 + 8) * LSTR + gc + 1] = acc[3];
        Arow[r0 * LSTR + gc + 8]       = acc[4];
        Arow[r0 * LSTR + gc + 9]       = acc[5];
        Arow[(r0 + 8) * LSTR + gc + 8] = acc[6];
        Arow[(r0 + 8) * LSTR + gc + 9] = acc[7];
        __syncthreads();
    }

    // phase 2: fused elementwise, write A_out, keep values in smem for topk
    const float* Am = g_Amean + ((size_t)b * NN + i0) * NN;
    const float* Sp = g_S + ((size_t)b * NN + i0) * NN;
    float* Ao = outA + ((size_t)(b * C1 + c) * NN + i0) * NN;
#pragma unroll 4
    for (int idx4 = tid; idx4 < 4096; idx4 += 256) {
        int r = idx4 >> 8, c4 = idx4 & 255;
        float4 am = ((const float4*)(Am + r * NN))[c4];
        float4 sv = ((const float4*)(Sp + r * NN))[c4];
        float4 mm = *(float4*)(Arow + r * LSTR + c4 * 4);
        float4 o;
        o.x = am.x + BETA / (1.f + __expf(-sv.x * mm.x * RSQRT10));
        o.y = am.y + BETA / (1.f + __expf(-sv.y * mm.y * RSQRT10));
        o.z = am.z + BETA / (1.f + __expf(-sv.z * mm.z * RSQRT10));
        o.w = am.w + BETA / (1.f + __expf(-sv.w * mm.w * RSQRT10));
        ((float4*)(Ao + r * NN))[c4] = o;
        *(float4*)(Arow + r * LSTR + c4 * 4) = o;
    }
    __syncthreads();

    // phase 3: top-5 per row, gather mask rows, max-reduce
    const float* maskc = mask + (size_t)(b * C1 + c) * NN * DD;
    float* Mo = outM + ((size_t)(b * C1 + c) * NN + i0) * DD;
#pragma unroll
    for (int rr = 0; rr < 2; rr++) {
        const int r = 2 * w + rr;
        const float* Ar = Arow + r * LSTR;
        int top[5];
#pragma unroll
        for (int p = 0; p < 5; p++) {
            float bv = -1e30f;
            int bi = NN;
            for (int i = lane; i < 1024; i += 32) {
                bool skip = false;
#pragma unroll
                for (int q = 0; q < 5; q++)
                    if (q < p && top[q] == i) skip = true;
                float v = Ar[i];
                if (!skip && v > bv) { bv = v; bi = i; }
            }
#pragma unroll
            for (int off = 16; off; off >>= 1) {
                float ov = __shfl_xor_sync(0xffffffffu, bv, off);
                int oi = __shfl_xor_sync(0xffffffffu, bi, off);
                if (ov > bv || (ov == bv && oi < bi)) { bv = ov; bi = oi; }
            }
            top[p] = bi;
        }
        float m0 = -1e30f, m1 = -1e30f;
#pragma unroll
        for (int p = 0; p < 5; p++) {
            const float* mr = maskc + (size_t)top[p] * DD;
            m0 = fmaxf(m0, mr[lane]);
            m1 = fmaxf(m1, mr[lane + 32]);
        }
        Mo[r * DD + lane] = m0;
        Mo[r * DD + lane + 32] = m1;
    }
}

// ---------------------------------------------------------------------------
extern "C" void kernel_launch(void* const* d_in, const int* in_sizes, int n_in,
                              void* d_out, int out_size) {
    (void)in_sizes; (void)n_in; (void)out_size;
    const float* x    = (const float*)d_in[0];
    const float* A    = (const float*)d_in[1];
    const float* mask = (const float*)d_in[2];
    float* outA = (float*)d_out;
    float* outM = outA + (size_t)BB * C1 * NN * NN;

    cudaFuncSetAttribute(k_S, cudaFuncAttributeMaxDynamicSharedMemorySize, SMEM_S);
    cudaFuncSetAttribute(k_main, cudaFuncAttributeMaxDynamicSharedMemorySize, SMEM_M);

    k_amean<<<(BB * NN * NN / 4 + 255) / 256, 256>>>(A);
    k_convx<<<(BB * CX * NN * DD / 4 + 255) / 256, 256>>>(x);
    k_convm<<<(BB * C1 * NN * DD / 4 + 255) / 256, 256>>>(mask);
    k_S<<<dim3(NN / 16, BB), 256, SMEM_S>>>();
    k_main<<<dim3(C1, NN / 16, BB), 256, SMEM_M>>>(mask, outA, outM);
}

// round 2
// speedup vs baseline: 1.4971x; 1.4971x over previous
#include <cuda_runtime.h>
#include <cuda_bf16.h>

// Problem constants
#define BB  4
#define CX  16
#define CA  8
#define C1  16
#define NN  1024
#define DD  64
#define BETA 0.02f
#define RSQRT10 0.3162277660168379f
#define NEGINF (-3.402823466e38f)

// Scratch (static __device__ arrays; no dynamic allocation)
__device__ __align__(16) float g_S[BB * NN * NN];                  // 16.8 MB final S
__device__ __align__(16) float g_Sp[8u * BB * NN * NN];            // 134 MB partial S (8 cgroups)
__device__ __align__(16) float g_Amean[BB * NN * NN];              // 16.8 MB
__device__ __align__(16) __nv_bfloat16 g_xbf[BB * CX * NN * DD];   // 8.4 MB
__device__ __align__(16) __nv_bfloat16 g_mbf[BB * C1 * NN * DD];   // 8.4 MB

// ---------------------------------------------------------------------------
// PTX helpers
// ---------------------------------------------------------------------------
__device__ __forceinline__ unsigned sptr(const void* p) {
    return (unsigned)__cvta_generic_to_shared(p);
}

__device__ __forceinline__ void ldsm4(unsigned a[4], unsigned addr) {
    asm volatile("ldmatrix.sync.aligned.m8n8.x4.shared.b16 {%0,%1,%2,%3}, [%4];"
                 : "=r"(a[0]), "=r"(a[1]), "=r"(a[2]), "=r"(a[3]) : "r"(addr));
}

__device__ __forceinline__ void mma16816(float c[4], const unsigned a[4],
                                         unsigned b0, unsigned b1) {
    asm volatile(
        "mma.sync.aligned.m16n8k16.row.col.f32.bf16.bf16.f32 "
        "{%0,%1,%2,%3}, {%4,%5,%6,%7}, {%8,%9}, {%0,%1,%2,%3};"
        : "+f"(c[0]), "+f"(c[1]), "+f"(c[2]), "+f"(c[3])
        : "r"(a[0]), "r"(a[1]), "r"(a[2]), "r"(a[3]), "r"(b0), "r"(b1));
}

__device__ __forceinline__ void cpasync16(unsigned dst, const void* src) {
    asm volatile("cp.async.cg.shared.global [%0], [%1], 16;" :: "r"(dst), "l"(src));
}
#define CP_COMMIT() asm volatile("cp.async.commit_group;")
#define CP_WAIT1()  asm volatile("cp.async.wait_group 1;")
#define CP_WAIT0()  asm volatile("cp.async.wait_group 0;")

// ---------------------------------------------------------------------------
// Swizzled bf16 tiles: [rows][64] bf16, 128B/row; 16B chunk' = chunk ^ (row&7)
// ---------------------------------------------------------------------------
__device__ __forceinline__ void pf_tile128(const __nv_bfloat16* src,
                                           __nv_bfloat16* dst, int tid) {
#pragma unroll
    for (int q = 0; q < 4; q++) {
        int id = tid + q * 256;
        int r = id >> 3, cc = id & 7;
        cpasync16(sptr(dst + r * 64 + ((cc ^ (r & 7)) << 3)), src + r * 64 + cc * 8);
    }
}

__device__ __forceinline__ void pf_tile64(const __nv_bfloat16* src,
                                          __nv_bfloat16* dst, int tid) {
#pragma unroll
    for (int q = 0; q < 2; q++) {
        int id = tid + q * 256;
        int r = id >> 3, cc = id & 7;
        cpasync16(sptr(dst + r * 64 + ((cc ^ (r & 7)) << 3)), src + r * 64 + cc * 8);
    }
}

// A fragments for a 16-row slice (rows x 64 k), cached in regs for all k-steps
__device__ __forceinline__ void load_afrag(const __nv_bfloat16* xi16, int lane,
                                           unsigned a[4][4]) {
    const int ar = (lane & 7) + (((lane >> 3) & 1) << 3);
    const int ak8 = lane >> 4;
#pragma unroll
    for (int ks = 0; ks < 4; ks++)
        ldsm4(a[ks], sptr(xi16 + ar * 64 + (((2 * ks + ak8) ^ (ar & 7)) << 3)));
}

// acc[8] += A(16x64) * B(rows n0..n0+15 of 64x64 tile)^T
__device__ __forceinline__ void subtile_mma(const __nv_bfloat16* bt, int n0, int lane,
                                            const unsigned a[4][4], float acc[8]) {
    const int m = lane >> 3;
    const int br = n0 + (lane & 7) + ((m >> 1) << 3);
    const int bk8 = m & 1;
#pragma unroll
    for (int ks = 0; ks < 4; ks++) {
        unsigned b[4];
        ldsm4(b, sptr(bt + br * 64 + (((2 * ks + bk8) ^ (br & 7)) << 3)));
        mma16816(acc, a[ks], b[0], b[1]);
        mma16816(acc + 4, a[ks], b[2], b[3]);
    }
}

// ---------------------------------------------------------------------------
// Prep kernels
// ---------------------------------------------------------------------------
__global__ void k_amean(const float* __restrict__ A) {
    int idx = blockIdx.x * blockDim.x + threadIdx.x;
    const int per_b = NN * NN / 4;
    if (idx >= BB * per_b) return;
    int b = idx / per_b;
    int r = idx - b * per_b;
    const float4* base = (const float4*)A + (size_t)b * CA * per_b + r;
    float4 s = make_float4(0.f, 0.f, 0.f, 0.f);
#pragma unroll
    for (int ca = 0; ca < CA; ca++) {
        float4 v = base[(size_t)ca * per_b];
        s.x += v.x; s.y += v.y; s.z += v.z; s.w += v.w;
    }
    s.x *= 0.125f; s.y *= 0.125f; s.z *= 0.125f; s.w *= 0.125f;
    ((float4*)g_Amean)[idx] = s;
}

__global__ void k_convx(const float* __restrict__ src) {
    int idx = blockIdx.x * blockDim.x + threadIdx.x;
    if (idx >= BB * CX * NN * DD / 4) return;
    float4 v = ((const float4*)src)[idx];
    __nv_bfloat162 p0 = __floats2bfloat162_rn(v.x, v.y);
    __nv_bfloat162 p1 = __floats2bfloat162_rn(v.z, v.w);
    uint2 u;
    u.x = *reinterpret_cast<unsigned*>(&p0);
    u.y = *reinterpret_cast<unsigned*>(&p1);
    ((uint2*)g_xbf)[idx] = u;
}

__global__ void k_convm(const float* __restrict__ src) {
    int idx = blockIdx.x * blockDim.x + threadIdx.x;
    if (idx >= BB * C1 * NN * DD / 4) return;
    float4 v = ((const float4*)src)[idx];
    __nv_bfloat162 p0 = __floats2bfloat162_rn(v.x, v.y);
    __nv_bfloat162 p1 = __floats2bfloat162_rn(v.z, v.w);
    uint2 u;
    u.x = *reinterpret_cast<unsigned*>(&p0);
    u.y = *reinterpret_cast<unsigned*>(&p1);
    ((uint2*)g_mbf)[idx] = u;
}

// ---------------------------------------------------------------------------
// k_S2: partial S for 2 channels per block.
// grid (itile=8, cg=8, b=4), 256 thr, warp w owns rows [w*16, w*16+16) of 128.
// Pass Z: row sums of exp(logit - P_row) (P = ||x_row||^2 pseudo-max).
// Pass S: recompute logits, accumulate exp*Zinv over both channels, write g_Sp.
// ---------------------------------------------------------------------------
#define KS_SMEM (2*128*64*2 + 2*2*64*64*2 + 2*128*4 + 2*128*4)

__global__ void __launch_bounds__(256, 2) k_S2() {
    extern __shared__ char sm[];
    __nv_bfloat16* xi  = (__nv_bfloat16*)sm;            // [2][128*64]
    __nv_bfloat16* xjb = xi + 2 * 128 * 64;             // [2 buf][2 ch][64*64]
    float* P  = (float*)(xjb + 2 * 2 * 64 * 64);        // [2][128]
    float* Zi = P + 2 * 128;                            // [2][128]

    const int tid = threadIdx.x, lane = tid & 31, w = tid >> 5;
    const int itile = blockIdx.x, cg = blockIdx.y, b = blockIdx.z;

    const __nv_bfloat16* xc0 = g_xbf + (size_t)(b * CX + cg * 2) * NN * DD;
    const __nv_bfloat16* xc1 = xc0 + NN * DD;

    pf_tile128(xc0 + itile * 128 * 64, xi, tid);
    pf_tile128(xc1 + itile * 128 * 64, xi + 128 * 64, tid);
    CP_COMMIT();
    pf_tile64(xc0, xjb, tid);
    pf_tile64(xc1, xjb + 64 * 64, tid);
    CP_COMMIT();
    CP_WAIT1();
    __syncthreads();

    // P = ||row||^2 (from bf16 values, matching mma products)
    {
        int c = tid >> 7, r = tid & 127;
        const __nv_bfloat16* row = xi + c * (128 * 64) + r * 64;
        float s = 0.f;
#pragma unroll
        for (int cc = 0; cc < 8; cc++) {
            const __nv_bfloat16* ch = row + ((cc ^ (r & 7)) << 3);
#pragma unroll
            for (int e = 0; e < 8; e++) {
                float v = __bfloat162float(ch[e]);
                s += v * v;
            }
        }
        P[c * 128 + r] = s;
    }
    __syncthreads();

    unsigned a0[4][4], a1[4][4];
    load_afrag(xi + w * 16 * 64, lane, a0);
    load_afrag(xi + 128 * 64 + w * 16 * 64, lane, a1);

    const int lr0 = w * 16 + (lane >> 2), lr1 = lr0 + 8;
    const float p00 = P[lr0], p01 = P[lr1], p10 = P[128 + lr0], p11 = P[128 + lr1];

    // ---- Pass Z ----
    float z[2][2] = {{0.f, 0.f}, {0.f, 0.f}};
    for (int jt = 0; jt < 16; jt++) {
        if (jt < 15) {
            __nv_bfloat16* nb = xjb + ((jt + 1) & 1) * 2 * 64 * 64;
            pf_tile64(xc0 + (jt + 1) * 64 * 64, nb, tid);
            pf_tile64(xc1 + (jt + 1) * 64 * 64, nb + 64 * 64, tid);
            CP_COMMIT(); CP_WAIT1();
        } else CP_WAIT0();
        __syncthreads();
        const __nv_bfloat16* bt = xjb + (jt & 1) * 2 * 64 * 64;
#pragma unroll
        for (int c = 0; c < 2; c++) {
            const float pa = c ? p10 : p00, pb = c ? p11 : p01;
#pragma unroll
            for (int n = 0; n < 4; n++) {
                float acc[8] = {0.f, 0.f, 0.f, 0.f, 0.f, 0.f, 0.f, 0.f};
                subtile_mma(bt + c * 64 * 64, n * 16, lane, c ? a1 : a0, acc);
                z[c][0] += __expf(acc[0] - pa) + __expf(acc[1] - pa)
                         + __expf(acc[4] - pa) + __expf(acc[5] - pa);
                z[c][1] += __expf(acc[2] - pb) + __expf(acc[3] - pb)
                         + __expf(acc[6] - pb) + __expf(acc[7] - pb);
            }
        }
        __syncthreads();
    }
    // quad reduce (lanes sharing a row differ in bits 0,1), write Zinv incl 1/16
#pragma unroll
    for (int c = 0; c < 2; c++)
#pragma unroll
        for (int rr = 0; rr < 2; rr++) {
            float v = z[c][rr];
            v += __shfl_xor_sync(0xffffffffu, v, 1);
            v += __shfl_xor_sync(0xffffffffu, v, 2);
            if ((lane & 3) == 0) Zi[c * 128 + (rr ? lr1 : lr0)] = 1.f / (16.f * v);
        }

    // prime pass S
    pf_tile64(xc0, xjb, tid);
    pf_tile64(xc1, xjb + 64 * 64, tid);
    CP_COMMIT();
    __syncthreads();   // Zi visible + buffers safe

    const float zi00 = Zi[lr0], zi01 = Zi[lr1];
    const float zi10 = Zi[128 + lr0], zi11 = Zi[128 + lr1];

    float* spBase = g_Sp + (size_t)(cg * BB + b) * NN * NN + (size_t)(itile * 128) * NN;

    for (int jt = 0; jt < 16; jt++) {
        if (jt < 15) {
            __nv_bfloat16* nb = xjb + ((jt + 1) & 1) * 2 * 64 * 64;
            pf_tile64(xc0 + (jt + 1) * 64 * 64, nb, tid);
            pf_tile64(xc1 + (jt + 1) * 64 * 64, nb + 64 * 64, tid);
            CP_COMMIT(); CP_WAIT1();
        } else CP_WAIT0();
        __syncthreads();
        const __nv_bfloat16* bt = xjb + (jt & 1) * 2 * 64 * 64;

        float Sa[4][8];
#pragma unroll
        for (int n = 0; n < 4; n++)
#pragma unroll
            for (int k = 0; k < 8; k++) Sa[n][k] = 0.f;

#pragma unroll
        for (int c = 0; c < 2; c++) {
            const float pa = c ? p10 : p00, pb = c ? p11 : p01;
            const float za = c ? zi10 : zi00, zb = c ? zi11 : zi01;
#pragma unroll
            for (int n = 0; n < 4; n++) {
                float acc[8] = {0.f, 0.f, 0.f, 0.f, 0.f, 0.f, 0.f, 0.f};
                subtile_mma(bt + c * 64 * 64, n * 16, lane, c ? a1 : a0, acc);
                Sa[n][0] += __expf(acc[0] - pa) * za;
                Sa[n][1] += __expf(acc[1] - pa) * za;
                Sa[n][4] += __expf(acc[4] - pa) * za;
                Sa[n][5] += __expf(acc[5] - pa) * za;
                Sa[n][2] += __expf(acc[2] - pb) * zb;
                Sa[n][3] += __expf(acc[3] - pb) * zb;
                Sa[n][6] += __expf(acc[6] - pb) * zb;
                Sa[n][7] += __expf(acc[7] - pb) * zb;
            }
        }
#pragma unroll
        for (int n = 0; n < 4; n++) {
            const int cb = jt * 64 + n * 16 + 2 * (lane & 3);
            *(float2*)(spBase + (size_t)lr0 * NN + cb)     = make_float2(Sa[n][0], Sa[n][1]);
            *(float2*)(spBase + (size_t)lr0 * NN + cb + 8) = make_float2(Sa[n][4], Sa[n][5]);
            *(float2*)(spBase + (size_t)lr1 * NN + cb)     = make_float2(Sa[n][2], Sa[n][3]);
            *(float2*)(spBase + (size_t)lr1 * NN + cb + 8) = make_float2(Sa[n][6], Sa[n][7]);
        }
        __syncthreads();
    }
}

// ---------------------------------------------------------------------------
// Reduce the 8 partial S slices into g_S
// ---------------------------------------------------------------------------
__global__ void k_sreduce() {
    int i = blockIdx.x * 256 + threadIdx.x;  // over BB*NN*NN/4 float4
    const float4* p = (const float4*)g_Sp;
    const size_t str = (size_t)BB * NN * NN / 4;
    float4 s = p[i];
#pragma unroll
    for (int g = 1; g < 8; g++) {
        float4 v = p[(size_t)g * str + i];
        s.x += v.x; s.y += v.y; s.z += v.z; s.w += v.w;
    }
    ((float4*)g_S)[i] = s;
}

// ---------------------------------------------------------------------------
// k_main2: per (itile128, c, b): mm GEMM streamed, fused sigmoid + A_out write,
// streaming per-lane top-5 + quad merge, gather + max.
// ---------------------------------------------------------------------------
#define KM_SMEM (128*64*2 + 2*64*64*2 + 128*5*4)

__device__ __forceinline__ void ins5(float x, int i, float v[5], int ix[5]) {
    if (x > v[4]) {
#pragma unroll
        for (int p = 0; p < 5; p++) {
            if (x > v[p]) {
                float tv = v[p]; v[p] = x; x = tv;
                int ti = ix[p]; ix[p] = i; i = ti;
            }
        }
    }
}

__device__ __forceinline__ void head5(const float v[5], const int ix[5], int ptr,
                                      float& hv, int& hi) {
    hv = NEGINF; hi = 0x7fffffff;
    if (ptr == 0)      { hv = v[0]; hi = ix[0]; }
    else if (ptr == 1) { hv = v[1]; hi = ix[1]; }
    else if (ptr == 2) { hv = v[2]; hi = ix[2]; }
    else if (ptr == 3) { hv = v[3]; hi = ix[3]; }
    else if (ptr == 4) { hv = v[4]; hi = ix[4]; }
}

// merge top5 across the 4 lanes of a quad; every lane returns winner indices
__device__ __forceinline__ void quad_merge5(const float v[5], const int ix[5],
                                            int wout[5]) {
    int ptr = 0;
#pragma unroll
    for (int t = 0; t < 5; t++) {
        float hv; int hi;
        head5(v, ix, ptr, hv, hi);
        const float mv = hv; const int mi = hi;
#pragma unroll
        for (int off = 1; off <= 2; off <<= 1) {
            float ov = __shfl_xor_sync(0xffffffffu, hv, off);
            int   oi = __shfl_xor_sync(0xffffffffu, hi, off);
            if (ov > hv || (ov == hv && oi < hi)) { hv = ov; hi = oi; }
        }
        wout[t] = hi;
        if (mv == hv && mi == hi) ptr++;
    }
}

__global__ void __launch_bounds__(256, 2) k_main2(const float* __restrict__ mask,
                                                  float* __restrict__ outA,
                                                  float* __restrict__ outM) {
    extern __shared__ char sm[];
    __nv_bfloat16* mi  = (__nv_bfloat16*)sm;       // [128*64]
    __nv_bfloat16* mjb = mi + 128 * 64;            // [2][64*64]
    int* topidx = (int*)(mjb + 2 * 64 * 64);       // [128][5]

    const int tid = threadIdx.x, lane = tid & 31, w = tid >> 5;
    const int itile = blockIdx.x, c = blockIdx.y, b = blockIdx.z;

    const __nv_bfloat16* mc = g_mbf + (size_t)(b * C1 + c) * NN * DD;
    pf_tile128(mc + itile * 128 * 64, mi, tid);
    CP_COMMIT();
    pf_tile64(mc, mjb, tid);
    CP_COMMIT();
    CP_WAIT1();
    __syncthreads();

    unsigned a[4][4];
    load_afrag(mi + w * 16 * 64, lane, a);

    const int lr0 = w * 16 + (lane >> 2), lr1 = lr0 + 8;
    const int gr0 = itile * 128 + lr0, gr1 = itile * 128 + lr1;

    const float* S0 = g_S + ((size_t)b * NN + gr0) * NN;
    const float* S1 = g_S + ((size_t)b * NN + gr1) * NN;
    const float* A0 = g_Amean + ((size_t)b * NN + gr0) * NN;
    const float* A1 = g_Amean + ((size_t)b * NN + gr1) * NN;
    float* O0 = outA + ((size_t)(b * C1 + c) * NN + gr0) * NN;
    float* O1 = outA + ((size_t)(b * C1 + c) * NN + gr1) * NN;

    float v0[5], v1[5]; int i0[5], i1[5];
#pragma unroll
    for (int p = 0; p < 5; p++) { v0[p] = NEGINF; v1[p] = NEGINF; i0[p] = 0x7fffffff; i1[p] = 0x7fffffff; }

    for (int jt = 0; jt < 16; jt++) {
        if (jt < 15) {
            pf_tile64(mc + (jt + 1) * 64 * 64, mjb + ((jt + 1) & 1) * 64 * 64, tid);
            CP_COMMIT(); CP_WAIT1();
        } else CP_WAIT0();
        __syncthreads();
        const __nv_bfloat16* bt = mjb + (jt & 1) * 64 * 64;
#pragma unroll
        for (int n = 0; n < 4; n++) {
            float acc[8] = {0.f, 0.f, 0.f, 0.f, 0.f, 0.f, 0.f, 0.f};
            subtile_mma(bt, n * 16, lane, a, acc);
            const int cb = jt * 64 + n * 16 + 2 * (lane & 3);

            float2 sA = *(const float2*)(S0 + cb), sB = *(const float2*)(S0 + cb + 8);
            float2 sC = *(const float2*)(S1 + cb), sD = *(const float2*)(S1 + cb + 8);
            float2 aA = *(const float2*)(A0 + cb), aB = *(const float2*)(A0 + cb + 8);
            float2 aC = *(const float2*)(A1 + cb), aD = *(const float2*)(A1 + cb + 8);

            float o0 = aA.x + BETA / (1.f + __expf(-sA.x * acc[0] * RSQRT10));
            float o1 = aA.y + BETA / (1.f + __expf(-sA.y * acc[1] * RSQRT10));
            float o4 = aB.x + BETA / (1.f + __expf(-sB.x * acc[4] * RSQRT10));
            float o5 = aB.y + BETA / (1.f + __expf(-sB.y * acc[5] * RSQRT10));
            float o2 = aC.x + BETA / (1.f + __expf(-sC.x * acc[2] * RSQRT10));
            float o3 = aC.y + BETA / (1.f + __expf(-sC.y * acc[3] * RSQRT10));
            float o6 = aD.x + BETA / (1.f + __expf(-sD.x * acc[6] * RSQRT10));
            float o7 = aD.y + BETA / (1.f + __expf(-sD.y * acc[7] * RSQRT10));

            *(float2*)(O0 + cb)     = make_float2(o0, o1);
            *(float2*)(O0 + cb + 8) = make_float2(o4, o5);
            *(float2*)(O1 + cb)     = make_float2(o2, o3);
            *(float2*)(O1 + cb + 8) = make_float2(o6, o7);

            ins5(o0, cb,     v0, i0); ins5(o1, cb + 1, v0, i0);
            ins5(o4, cb + 8, v0, i0); ins5(o5, cb + 9, v0, i0);
            ins5(o2, cb,     v1, i1); ins5(o3, cb + 1, v1, i1);
            ins5(o6, cb + 8, v1, i1); ins5(o7, cb + 9, v1, i1);
        }
        __syncthreads();
    }

    // merge per-row top5 across quads, stash indices
    {
        int wout[5];
        quad_merge5(v0, i0, wout);
        if ((lane & 3) == 0)
#pragma unroll
            for (int t = 0; t < 5; t++) topidx[lr0 * 5 + t] = wout[t];
        quad_merge5(v1, i1, wout);
        if ((lane & 3) == 0)
#pragma unroll
            for (int t = 0; t < 5; t++) topidx[lr1 * 5 + t] = wout[t];
    }
    __syncthreads();

    // gather top-5 mask rows + max  (original f32 mask)
    const float* mkb = mask + (size_t)(b * C1 + c) * NN * DD;
    float* Mo = outM + ((size_t)(b * C1 + c) * NN + itile * 128) * DD;
    for (int rr = 0; rr < 16; rr++) {
        const int lr = w * 16 + rr;
        float m0 = NEGINF, m1 = NEGINF;
#pragma unroll
        for (int p = 0; p < 5; p++) {
            const float* mr = mkb + (size_t)topidx[lr * 5 + p] * DD;
            m0 = fmaxf(m0, mr[lane]);
            m1 = fmaxf(m1, mr[lane + 32]);
        }
        Mo[(size_t)lr * DD + lane] = m0;
        Mo[(size_t)lr * DD + lane + 32] = m1;
    }
}

// ---------------------------------------------------------------------------
extern "C" void kernel_launch(void* const* d_in, const int* in_sizes, int n_in,
                              void* d_out, int out_size) {
    (void)in_sizes; (void)n_in; (void)out_size;
    const float* x    = (const float*)d_in[0];
    const float* A    = (const float*)d_in[1];
    const float* mask = (const float*)d_in[2];
    float* outA = (float*)d_out;
    float* outM = outA + (size_t)BB * C1 * NN * NN;

    cudaFuncSetAttribute(k_S2, cudaFuncAttributeMaxDynamicSharedMemorySize, KS_SMEM);
    cudaFuncSetAttribute(k_main2, cudaFuncAttributeMaxDynamicSharedMemorySize, KM_SMEM);

    k_amean<<<(BB * NN * NN / 4 + 255) / 256, 256>>>(A);
    k_convx<<<(BB * CX * NN * DD / 4 + 255) / 256, 256>>>(x);
    k_convm<<<(BB * C1 * NN * DD / 4 + 255) / 256, 256>>>(mask);
    k_S2<<<dim3(NN / 128, 8, BB), 256, KS_SMEM>>>();
    k_sreduce<<<BB * NN * NN / 4 / 256, 256>>>();
    k_main2<<<dim3(NN / 128, C1, BB), 256, KM_SMEM>>>(mask, outA, outM);
}

// round 4
// speedup vs baseline: 1.6551x; 1.1056x over previous
#include <cuda_runtime.h>
#include <cuda_bf16.h>

// Problem constants
#define BB  4
#define CX  16
#define CA  8
#define C1  16
#define NN  1024
#define DD  64
#define NEGINF (-3.402823466e38f)

// 0.02*sigmoid(z) = 0.01 + 0.01*tanh(z/2); z = S*mm/sqrt(10)
// -> store S' = S * 0.5/sqrt(10), A' = Amean + 0.01; out = fma(0.01, tanh(S'*mm), A')
#define SSCALE 0.15811388300841898f

// Scratch (static __device__ arrays; no dynamic allocation)
__device__ __align__(16) float g_Sp[8u * BB * NN * NN];            // 134 MB partial S
__device__ __align__(16) float g_SA[2u * BB * NN * NN];            // 33.6 MB (S',A') interleaved
__device__ __align__(16) __nv_bfloat16 g_xbf[BB * CX * NN * DD];   // 8.4 MB
__device__ __align__(16) __nv_bfloat16 g_mbf[BB * C1 * NN * DD];   // 8.4 MB

// ---------------------------------------------------------------------------
// PTX helpers
// ---------------------------------------------------------------------------
__device__ __forceinline__ unsigned sptr(const void* p) {
    return (unsigned)__cvta_generic_to_shared(p);
}

__device__ __forceinline__ void ldsm4(unsigned a[4], unsigned addr) {
    asm volatile("ldmatrix.sync.aligned.m8n8.x4.shared.b16 {%0,%1,%2,%3}, [%4];"
                 : "=r"(a[0]), "=r"(a[1]), "=r"(a[2]), "=r"(a[3]) : "r"(addr));
}

__device__ __forceinline__ void mma16816(float c[4], const unsigned a[4],
                                         unsigned b0, unsigned b1) {
    asm volatile(
        "mma.sync.aligned.m16n8k16.row.col.f32.bf16.bf16.f32 "
        "{%0,%1,%2,%3}, {%4,%5,%6,%7}, {%8,%9}, {%0,%1,%2,%3};"
        : "+f"(c[0]), "+f"(c[1]), "+f"(c[2]), "+f"(c[3])
        : "r"(a[0]), "r"(a[1]), "r"(a[2]), "r"(a[3]), "r"(b0), "r"(b1));
}

__device__ __forceinline__ void cpasync16(unsigned dst, const void* src) {
    asm volatile("cp.async.cg.shared.global [%0], [%1], 16;" :: "r"(dst), "l"(src));
}
#define CP_COMMIT() asm volatile("cp.async.commit_group;")
#define CP_WAIT1()  asm volatile("cp.async.wait_group 1;")
#define CP_WAIT0()  asm volatile("cp.async.wait_group 0;")

__device__ __forceinline__ float tanhap(float x) {
    float r;
    asm("tanh.approx.f32 %0, %1;" : "=f"(r) : "f"(x));
    return r;
}

// ---------------------------------------------------------------------------
// Swizzled bf16 tiles: [rows][64] bf16, 128B/row; 16B chunk' = chunk ^ (row&7)
// ---------------------------------------------------------------------------
__device__ __forceinline__ void pf_tile128(const __nv_bfloat16* src,
                                           __nv_bfloat16* dst, int tid) {
#pragma unroll
    for (int q = 0; q < 4; q++) {
        int id = tid + q * 256;
        int r = id >> 3, cc = id & 7;
        cpasync16(sptr(dst + r * 64 + ((cc ^ (r & 7)) << 3)), src + r * 64 + cc * 8);
    }
}

__device__ __forceinline__ void pf_tile64(const __nv_bfloat16* src,
                                          __nv_bfloat16* dst, int tid) {
#pragma unroll
    for (int q = 0; q < 2; q++) {
        int id = tid + q * 256;
        int r = id >> 3, cc = id & 7;
        cpasync16(sptr(dst + r * 64 + ((cc ^ (r & 7)) << 3)), src + r * 64 + cc * 8);
    }
}

// A fragments for a 16-row slice, cached in regs
__device__ __forceinline__ void load_afrag(const __nv_bfloat16* xi16, int lane,
                                           unsigned a[4][4]) {
    const int ar = (lane & 7) + (((lane >> 3) & 1) << 3);
    const int ak8 = lane >> 4;
#pragma unroll
    for (int ks = 0; ks < 4; ks++)
        ldsm4(a[ks], sptr(xi16 + ar * 64 + (((2 * ks + ak8) ^ (ar & 7)) << 3)));
}

// acc[8] += A(16x64) * B(rows n0..n0+15 of 64x64 tile)^T
__device__ __forceinline__ void subtile_mma(const __nv_bfloat16* bt, int n0, int lane,
                                            const unsigned a[4][4], float acc[8]) {
    const int m = lane >> 3;
    const int br = n0 + (lane & 7) + ((m >> 1) << 3);
    const int bk8 = m & 1;
#pragma unroll
    for (int ks = 0; ks < 4; ks++) {
        unsigned b[4];
        ldsm4(b, sptr(bt + br * 64 + (((2 * ks + bk8) ^ (br & 7)) << 3)));
        mma16816(acc, a[ks], b[0], b[1]);
        mma16816(acc + 4, a[ks], b[2], b[3]);
    }
}

// ---------------------------------------------------------------------------
// Prep: bf16 conversions
// ---------------------------------------------------------------------------
__global__ void k_convx(const float* __restrict__ src) {
    int idx = blockIdx.x * blockDim.x + threadIdx.x;
    if (idx >= BB * CX * NN * DD / 4) return;
    float4 v = ((const float4*)src)[idx];
    __nv_bfloat162 p0 = __floats2bfloat162_rn(v.x, v.y);
    __nv_bfloat162 p1 = __floats2bfloat162_rn(v.z, v.w);
    uint2 u;
    u.x = *reinterpret_cast<unsigned*>(&p0);
    u.y = *reinterpret_cast<unsigned*>(&p1);
    ((uint2*)g_xbf)[idx] = u;
}

__global__ void k_convm(const float* __restrict__ src) {
    int idx = blockIdx.x * blockDim.x + threadIdx.x;
    if (idx >= BB * C1 * NN * DD / 4) return;
    float4 v = ((const float4*)src)[idx];
    __nv_bfloat162 p0 = __floats2bfloat162_rn(v.x, v.y);
    __nv_bfloat162 p1 = __floats2bfloat162_rn(v.z, v.w);
    uint2 u;
    u.x = *reinterpret_cast<unsigned*>(&p0);
    u.y = *reinterpret_cast<unsigned*>(&p1);
    ((uint2*)g_mbf)[idx] = u;
}

// ---------------------------------------------------------------------------
// k_S3: partial S for 2 channels, 64-row tiles.
// grid (itile=16, cg=8, b=4) = 512 blocks, 256 thr.
// warp w: wr=w&3 row strip [wr*16,+16), wc=w>>2 col half of each 64-col j-tile.
// Pass Z: per-warp partial row sums of exp(logit - P_row), combined in smem.
// Pass S: recompute logits, write normalized partials summed over 2 channels.
// ---------------------------------------------------------------------------
#define KS3_SMEM (2*64*64*2 + 2*2*64*64*2 + 2*64*4 + 2*64*2*4 + 2*64*4)

__global__ void __launch_bounds__(256, 3) k_S3() {
    extern __shared__ char sm[];
    __nv_bfloat16* xi  = (__nv_bfloat16*)sm;            // [2ch][64*64]
    __nv_bfloat16* xjb = xi + 2 * 64 * 64;              // [2buf][2ch][64*64]
    float* P  = (float*)(xjb + 2 * 2 * 64 * 64);        // [2][64]
    float* Zw = P + 2 * 64;                             // [2][64][2]
    float* Zi = Zw + 2 * 64 * 2;                        // [2][64]

    const int tid = threadIdx.x, lane = tid & 31, w = tid >> 5;
    const int wr = w & 3, wc = w >> 2;
    const int itile = blockIdx.x, cg = blockIdx.y, b = blockIdx.z;

    const __nv_bfloat16* xc0 = g_xbf + (size_t)(b * CX + cg * 2) * NN * DD;
    const __nv_bfloat16* xc1 = xc0 + NN * DD;

    pf_tile64(xc0 + itile * 64 * 64, xi, tid);
    pf_tile64(xc1 + itile * 64 * 64, xi + 64 * 64, tid);
    CP_COMMIT();
    pf_tile64(xc0, xjb, tid);
    pf_tile64(xc1, xjb + 64 * 64, tid);
    CP_COMMIT();
    CP_WAIT1();
    __syncthreads();

    // P = ||row||^2 from bf16 values
    if (tid < 128) {
        int c = tid >> 6, r = tid & 63;
        const __nv_bfloat16* row = xi + c * 4096 + r * 64;
        float s = 0.f;
#pragma unroll
        for (int cc = 0; cc < 8; cc++) {
            const __nv_bfloat16* ch = row + ((cc ^ (r & 7)) << 3);
#pragma unroll
            for (int e = 0; e < 8; e++) {
                float v = __bfloat162float(ch[e]);
                s += v * v;
            }
        }
        P[c * 64 + r] = s;
    }
    __syncthreads();

    unsigned a0[4][4], a1[4][4];
    load_afrag(xi + wr * 16 * 64, lane, a0);
    load_afrag(xi + 4096 + wr * 16 * 64, lane, a1);

    const int lr0 = wr * 16 + (lane >> 2), lr1 = lr0 + 8;
    const float p00 = P[lr0], p01 = P[lr1], p10 = P[64 + lr0], p11 = P[64 + lr1];

    // ---- Pass Z ----
    float z00 = 0.f, z01 = 0.f, z10 = 0.f, z11 = 0.f;
    for (int jt = 0; jt < 16; jt++) {
        if (jt < 15) {
            __nv_bfloat16* nb = xjb + ((jt + 1) & 1) * 8192;
            pf_tile64(xc0 + (jt + 1) * 64 * 64, nb, tid);
            pf_tile64(xc1 + (jt + 1) * 64 * 64, nb + 4096, tid);
            CP_COMMIT(); CP_WAIT1();
        } else CP_WAIT0();
        __syncthreads();
        const __nv_bfloat16* bt = xjb + (jt & 1) * 8192;
#pragma unroll
        for (int nn = 0; nn < 2; nn++) {
            const int n0 = (wc * 2 + nn) * 16;
            {
                float acc[8] = {0.f, 0.f, 0.f, 0.f, 0.f, 0.f, 0.f, 0.f};
                subtile_mma(bt, n0, lane, a0, acc);
                z00 += __expf(acc[0] - p00) + __expf(acc[1] - p00)
                     + __expf(acc[4] - p00) + __expf(acc[5] - p00);
                z01 += __expf(acc[2] - p01) + __expf(acc[3] - p01)
                     + __expf(acc[6] - p01) + __expf(acc[7] - p01);
            }
            {
                float acc[8] = {0.f, 0.f, 0.f, 0.f, 0.f, 0.f, 0.f, 0.f};
                subtile_mma(bt + 4096, n0, lane, a1, acc);
                z10 += __expf(acc[0] - p10) + __expf(acc[1] - p10)
                     + __expf(acc[4] - p10) + __expf(acc[5] - p10);
                z11 += __expf(acc[2] - p11) + __expf(acc[3] - p11)
                     + __expf(acc[6] - p11) + __expf(acc[7] - p11);
            }
        }
        __syncthreads();
    }
    // quad-reduce, write per-warp partials
    z00 += __shfl_xor_sync(0xffffffffu, z00, 1); z00 += __shfl_xor_sync(0xffffffffu, z00, 2);
    z01 += __shfl_xor_sync(0xffffffffu, z01, 1); z01 += __shfl_xor_sync(0xffffffffu, z01, 2);
    z10 += __shfl_xor_sync(0xffffffffu, z10, 1); z10 += __shfl_xor_sync(0xffffffffu, z10, 2);
    z11 += __shfl_xor_sync(0xffffffffu, z11, 1); z11 += __shfl_xor_sync(0xffffffffu, z11, 2);
    if ((lane & 3) == 0) {
        Zw[lr0 * 2 + wc]       = z00;
        Zw[lr1 * 2 + wc]       = z01;
        Zw[128 + lr0 * 2 + wc] = z10;
        Zw[128 + lr1 * 2 + wc] = z11;
    }
    __syncthreads();
    if (tid < 128) {
        int c = tid >> 6, r = tid & 63;
        Zi[c * 64 + r] = 1.f / (16.f * (Zw[c * 128 + r * 2] + Zw[c * 128 + r * 2 + 1]));
    }
    // prime pass S
    pf_tile64(xc0, xjb, tid);
    pf_tile64(xc1, xjb + 4096, tid);
    CP_COMMIT();
    __syncthreads();   // Zi visible + buffers safe

    const float zi00 = Zi[lr0], zi01 = Zi[lr1];
    const float zi10 = Zi[64 + lr0], zi11 = Zi[64 + lr1];

    float* spBase = g_Sp + (size_t)(cg * BB + b) * NN * NN + (size_t)(itile * 64) * NN;

    for (int jt = 0; jt < 16; jt++) {
        if (jt < 15) {
            __nv_bfloat16* nb = xjb + ((jt + 1) & 1) * 8192;
            pf_tile64(xc0 + (jt + 1) * 64 * 64, nb, tid);
            pf_tile64(xc1 + (jt + 1) * 64 * 64, nb + 4096, tid);
            CP_COMMIT(); CP_WAIT1();
        } else CP_WAIT0();
        __syncthreads();
        const __nv_bfloat16* bt = xjb + (jt & 1) * 8192;

#pragma unroll
        for (int nn = 0; nn < 2; nn++) {
            const int n = wc * 2 + nn;
            float Sa[8];
#pragma unroll
            for (int k = 0; k < 8; k++) Sa[k] = 0.f;
            {
                float acc[8] = {0.f, 0.f, 0.f, 0.f, 0.f, 0.f, 0.f, 0.f};
                subtile_mma(bt, n * 16, lane, a0, acc);
                Sa[0] += __expf(acc[0] - p00) * zi00;
                Sa[1] += __expf(acc[1] - p00) * zi00;
                Sa[4] += __expf(acc[4] - p00) * zi00;
                Sa[5] += __expf(acc[5] - p00) * zi00;
                Sa[2] += __expf(acc[2] - p01) * zi01;
                Sa[3] += __expf(acc[3] - p01) * zi01;
                Sa[6] += __expf(acc[6] - p01) * zi01;
                Sa[7] += __expf(acc[7] - p01) * zi01;
            }
            {
                float acc[8] = {0.f, 0.f, 0.f, 0.f, 0.f, 0.f, 0.f, 0.f};
                subtile_mma(bt + 4096, n * 16, lane, a1, acc);
                Sa[0] += __expf(acc[0] - p10) * zi10;
                Sa[1] += __expf(acc[1] - p10) * zi10;
                Sa[4] += __expf(acc[4] - p10) * zi10;
                Sa[5] += __expf(acc[5] - p10) * zi10;
                Sa[2] += __expf(acc[2] - p11) * zi11;
                Sa[3] += __expf(acc[3] - p11) * zi11;
                Sa[6] += __expf(acc[6] - p11) * zi11;
                Sa[7] += __expf(acc[7] - p11) * zi11;
            }
            const int cb = jt * 64 + n * 16 + 2 * (lane & 3);
            *(float2*)(spBase + (size_t)lr0 * NN + cb)     = make_float2(Sa[0], Sa[1]);
            *(float2*)(spBase + (size_t)lr0 * NN + cb + 8) = make_float2(Sa[4], Sa[5]);
            *(float2*)(spBase + (size_t)lr1 * NN + cb)     = make_float2(Sa[2], Sa[3]);
            *(float2*)(spBase + (size_t)lr1 * NN + cb + 8) = make_float2(Sa[6], Sa[7]);
        }
        __syncthreads();
    }
}

// ---------------------------------------------------------------------------
// k_sreduce2: sum 8 partial S slices + mean of A over CA, write interleaved
// (S*SSCALE, Amean+0.01) pairs.
// ---------------------------------------------------------------------------
__global__ void k_sreduce2(const float* __restrict__ A) {
    int i = blockIdx.x * 256 + threadIdx.x;   // over BB*NN*NN/4 float4 groups
    const int per_b = NN * NN / 4;
    int b = i / per_b;
    int r = i - b * per_b;

    const float4* sp = (const float4*)g_Sp;
    float4 s = sp[(size_t)b * per_b + r];
#pragma unroll
    for (int g = 1; g < 8; g++) {
        float4 v = sp[(size_t)(g * BB + b) * per_b + r];
        s.x += v.x; s.y += v.y; s.z += v.z; s.w += v.w;
    }
    const float4* ap = (const float4*)A + (size_t)b * CA * per_b + r;
    float4 a = ap[0];
#pragma unroll
    for (int ch = 1; ch < CA; ch++) {
        float4 v = ap[(size_t)ch * per_b];
        a.x += v.x; a.y += v.y; a.z += v.z; a.w += v.w;
    }
    float4 o1, o2;
    o1.x = s.x * SSCALE; o1.y = a.x * 0.125f + 0.01f;
    o1.z = s.y * SSCALE; o1.w = a.y * 0.125f + 0.01f;
    o2.x = s.z * SSCALE; o2.y = a.z * 0.125f + 0.01f;
    o2.z = s.w * SSCALE; o2.w = a.w * 0.125f + 0.01f;
    float4* out = (float4*)g_SA + (size_t)i * 2;
    out[0] = o1;
    out[1] = o2;
}

// ---------------------------------------------------------------------------
// k_main3: per (itile128, c, b): mm GEMM streamed; SA prefetched one subtile
// ahead into regs; A_out = fma(0.01, tanh(S'*mm), A'); streaming top-5;
// gather + max.
// ---------------------------------------------------------------------------
#define KM_SMEM (128*64*2 + 2*64*64*2 + 128*5*4)

__device__ __forceinline__ void ins5(float x, int i, float v[5], int ix[5]) {
    if (x > v[4]) {
#pragma unroll
        for (int p = 0; p < 5; p++) {
            if (x > v[p]) {
                float tv = v[p]; v[p] = x; x = tv;
                int ti = ix[p]; ix[p] = i; i = ti;
            }
        }
    }
}

__device__ __forceinline__ void head5(const float v[5], const int ix[5], int ptr,
                                      float& hv, int& hi) {
    hv = NEGINF; hi = 0x7fffffff;
    if (ptr == 0)      { hv = v[0]; hi = ix[0]; }
    else if (ptr == 1) { hv = v[1]; hi = ix[1]; }
    else if (ptr == 2) { hv = v[2]; hi = ix[2]; }
    else if (ptr == 3) { hv = v[3]; hi = ix[3]; }
    else if (ptr == 4) { hv = v[4]; hi = ix[4]; }
}

__device__ __forceinline__ void quad_merge5(const float v[5], const int ix[5],
                                            int wout[5]) {
    int ptr = 0;
#pragma unroll
    for (int t = 0; t < 5; t++) {
        float hv; int hi;
        head5(v, ix, ptr, hv, hi);
        const float mv = hv; const int mi = hi;
#pragma unroll
        for (int off = 1; off <= 2; off <<= 1) {
            float ov = __shfl_xor_sync(0xffffffffu, hv, off);
            int   oi = __shfl_xor_sync(0xffffffffu, hi, off);
            if (ov > hv || (ov == hv && oi < hi)) { hv = ov; hi = oi; }
        }
        wout[t] = hi;
        if (mv == hv && mi == hi) ptr++;
    }
}

__global__ void __launch_bounds__(256, 2) k_main3(const float* __restrict__ mask,
                                                  float* __restrict__ outA,
                                                  float* __restrict__ outM) {
    extern __shared__ char sm[];
    __nv_bfloat16* mi  = (__nv_bfloat16*)sm;       // [128*64]
    __nv_bfloat16* mjb = mi + 128 * 64;            // [2][64*64]
    int* topidx = (int*)(mjb + 2 * 64 * 64);       // [128][5]

    const int tid = threadIdx.x, lane = tid & 31, w = tid >> 5;
    const int itile = blockIdx.x, c = blockIdx.y, b = blockIdx.z;

    const __nv_bfloat16* mc = g_mbf + (size_t)(b * C1 + c) * NN * DD;
    pf_tile128(mc + itile * 128 * 64, mi, tid);
    CP_COMMIT();
    pf_tile64(mc, mjb, tid);
    CP_COMMIT();
    CP_WAIT1();
    __syncthreads();

    unsigned a[4][4];
    load_afrag(mi + w * 16 * 64, lane, a);

    const int lr0 = w * 16 + (lane >> 2), lr1 = lr0 + 8;
    const int gr0 = itile * 128 + lr0, gr1 = itile * 128 + lr1;

    const float* SA0 = g_SA + ((size_t)b * NN + gr0) * NN * 2;
    const float* SA1 = g_SA + ((size_t)b * NN + gr1) * NN * 2;
    float* O0 = outA + ((size_t)(b * C1 + c) * NN + gr0) * NN;
    float* O1 = outA + ((size_t)(b * C1 + c) * NN + gr1) * NN;

    float v0[5], v1[5]; int i0[5], i1[5];
#pragma unroll
    for (int p = 0; p < 5; p++) {
        v0[p] = NEGINF; v1[p] = NEGINF; i0[p] = 0x7fffffff; i1[p] = 0x7fffffff;
    }

    const int lq = 2 * (lane & 3);

    for (int jt = 0; jt < 16; jt++) {
        if (jt < 15) {
            pf_tile64(mc + (jt + 1) * 64 * 64, mjb + ((jt + 1) & 1) * 64 * 64, tid);
            CP_COMMIT();
        }
        // prefetch SA for n=0 of this jt (global->reg, independent of smem)
        float4 sa[2][4];
        {
            const int cb = jt * 64 + lq;
            sa[0][0] = *(const float4*)(SA0 + 2 * cb);
            sa[0][1] = *(const float4*)(SA0 + 2 * (cb + 8));
            sa[0][2] = *(const float4*)(SA1 + 2 * cb);
            sa[0][3] = *(const float4*)(SA1 + 2 * (cb + 8));
        }
        if (jt < 15) { CP_WAIT1(); } else { CP_WAIT0(); }
        __syncthreads();
        const __nv_bfloat16* bt = mjb + (jt & 1) * 64 * 64;

#pragma unroll
        for (int n = 0; n < 4; n++) {
            if (n < 3) {  // prefetch SA for n+1
                const int cbn = jt * 64 + (n + 1) * 16 + lq;
                sa[(n + 1) & 1][0] = *(const float4*)(SA0 + 2 * cbn);
                sa[(n + 1) & 1][1] = *(const float4*)(SA0 + 2 * (cbn + 8));
                sa[(n + 1) & 1][2] = *(const float4*)(SA1 + 2 * cbn);
                sa[(n + 1) & 1][3] = *(const float4*)(SA1 + 2 * (cbn + 8));
            }
            float acc[8] = {0.f, 0.f, 0.f, 0.f, 0.f, 0.f, 0.f, 0.f};
            subtile_mma(bt, n * 16, lane, a, acc);

            const float4 q0 = sa[n & 1][0], q1 = sa[n & 1][1];
            const float4 q2 = sa[n & 1][2], q3 = sa[n & 1][3];
            const int cb = jt * 64 + n * 16 + lq;

            float o0 = fmaf(0.01f, tanhap(q0.x * acc[0]), q0.y);
            float o1 = fmaf(0.01f, tanhap(q0.z * acc[1]), q0.w);
            float o4 = fmaf(0.01f, tanhap(q1.x * acc[4]), q1.y);
            float o5 = fmaf(0.01f, tanhap(q1.z * acc[5]), q1.w);
            float o2 = fmaf(0.01f, tanhap(q2.x * acc[2]), q2.y);
            float o3 = fmaf(0.01f, tanhap(q2.z * acc[3]), q2.w);
            float o6 = fmaf(0.01f, tanhap(q3.x * acc[6]), q3.y);
            float o7 = fmaf(0.01f, tanhap(q3.z * acc[7]), q3.w);

            *(float2*)(O0 + cb)     = make_float2(o0, o1);
            *(float2*)(O0 + cb + 8) = make_float2(o4, o5);
            *(float2*)(O1 + cb)     = make_float2(o2, o3);
            *(float2*)(O1 + cb + 8) = make_float2(o6, o7);

            ins5(o0, cb,     v0, i0); ins5(o1, cb + 1, v0, i0);
            ins5(o4, cb + 8, v0, i0); ins5(o5, cb + 9, v0, i0);
            ins5(o2, cb,     v1, i1); ins5(o3, cb + 1, v1, i1);
            ins5(o6, cb + 8, v1, i1); ins5(o7, cb + 9, v1, i1);
        }
        __syncthreads();
    }

    // merge per-row top5 across quads, stash indices
    {
        int wout[5];
        quad_merge5(v0, i0, wout);
        if ((lane & 3) == 0)
#pragma unroll
            for (int t = 0; t < 5; t++) topidx[lr0 * 5 + t] = wout[t];
        quad_merge5(v1, i1, wout);
        if ((lane & 3) == 0)
#pragma unroll
            for (int t = 0; t < 5; t++) topidx[lr1 * 5 + t] = wout[t];
    }
    __syncthreads();

    // gather top-5 mask rows + max (original f32 mask)
    const float* mkb = mask + (size_t)(b * C1 + c) * NN * DD;
    float* Mo = outM + ((size_t)(b * C1 + c) * NN + itile * 128) * DD;
    for (int rr = 0; rr < 16; rr++) {
        const int lr = w * 16 + rr;
        float m0 = NEGINF, m1 = NEGINF;
#pragma unroll
        for (int p = 0; p < 5; p++) {
            const float* mr = mkb + (size_t)topidx[lr * 5 + p] * DD;
            m0 = fmaxf(m0, mr[lane]);
            m1 = fmaxf(m1, mr[lane + 32]);
        }
        Mo[(size_t)lr * DD + lane] = m0;
        Mo[(size_t)lr * DD + lane + 32] = m1;
    }
}

// ---------------------------------------------------------------------------
extern "C" void kernel_launch(void* const* d_in, const int* in_sizes, int n_in,
                              void* d_out, int out_size) {
    (void)in_sizes; (void)n_in; (void)out_size;
    const float* x    = (const float*)d_in[0];
    const float* A    = (const float*)d_in[1];
    const float* mask = (const float*)d_in[2];
    float* outA = (float*)d_out;
    float* outM = outA + (size_t)BB * C1 * NN * NN;

    cudaFuncSetAttribute(k_S3, cudaFuncAttributeMaxDynamicSharedMemorySize, KS3_SMEM);
    cudaFuncSetAttribute(k_main3, cudaFuncAttributeMaxDynamicSharedMemorySize, KM_SMEM);

    k_convx<<<(BB * CX * NN * DD / 4 + 255) / 256, 256>>>(x);
    k_convm<<<(BB * C1 * NN * DD / 4 + 255) / 256, 256>>>(mask);
    k_S3<<<dim3(16, 8, BB), 256, KS3_SMEM>>>();
    k_sreduce2<<<BB * NN * NN / 4 / 256, 256>>>(A);
    k_main3<<<dim3(8, C1, BB), 256, KM_SMEM>>>(mask, outA, outM);
}